// round 17
// baseline (speedup 1.0000x reference)
#include <cuda_runtime.h>
#include <cstdint>

// LocalPatternExtractor_82222853915140 — FINAL kernel (converged, R16).
//
// The reference forward output is identically zero:
//   quantize_pot_ste clips round(mem*128) to [-128, 127], so the quantized
//   membrane potential is at most 127/128 = 0.9921875 < THRESHOLD (1.0).
//   The forward spike value is the hard indicator (mem >= 1.0) — always
//   false — so acc stays 0 over all 4 timesteps: out = zeros(16,256,5000),
//   reg_loss = 0.01 * 0 = 0. (Confirmed rel_err = 0.0, rounds 2-16.)
//
// The problem therefore reduces to an 82 MB zero-fill. Design space mapped
// and closed over rounds 2-14:
//   - SM-originated stores (STG.128 4.0 / STG.256 5.7 / TMA bulk 5.8 /
//     STG+TMA combined 5.7 TB/s): hard chip write-acceptance cap ~5.8 TB/s,
//     measured 4 independent ways (dirty set lives in the 126MB L2; ncu
//     "L2=48%" is the saturated write port, DRAM idle).
//   - Single kernel node would need 6.55 TB/s to win -> ruled out.
//   - memset-node || kernel-node fork-join: paths DO add on the device
//     (~10-11 TB/s aggregate), but cross-queue graph replay overhead
//     (~6-8us, irreducible: join is mandatory for capture) makes best-case
//     ~15.9us.
//   - Same-stream extra nodes: +2.7us each.
//   - Single graph memset node: CE-class fill (~6.7 TB/s, above the SM cap)
//     + cheapest replay -> 14.8us end-to-end, stable to +-0.03us. Optimal.

extern "C" void kernel_launch(void* const* d_in, const int* in_sizes, int n_in,
                              void* d_out, int out_size) {
    (void)d_in; (void)in_sizes; (void)n_in;
    // Zero the entire fp32 output (20,480,000 spike rates + reg_loss scalar).
    cudaMemsetAsync(d_out, 0, (size_t)out_size * sizeof(float), 0);
}